// round 1
// baseline (speedup 1.0000x reference)
#include <cuda_runtime.h>
#include <cuda_bf16.h>

// Problem shape (fixed by the dataset): x1 [B,N1,1], x2 [B,N2,1], scale [1]
// out [B, N1, N2] fp32 = exp(-(x1-x2)^2 / (2*scale^2))
#define B_DIM   4
#define N1_DIM  8192
#define N2_DIM  8192

// Each CTA owns one output row (b, n1): 8192 floats = 2048 float4.
// 256 threads x 8 float4 each. Per element: 2 FFMA + 1 MUFU.EX2.
//   exp(-(a-x)^2 * K) = exp2( C*x^2 + Bc*x + A )
//   with Kl = log2(e)/(2 s^2),  C = -Kl,  Bc = 2 a Kl,  A = -a^2 Kl
__global__ __launch_bounds__(256) void rbf_row_kernel(
    const float* __restrict__ x1,
    const float* __restrict__ x2,
    const float* __restrict__ scale,
    float* __restrict__ out)
{
    const int row = blockIdx.x;            // b * N1 + n1
    const int b   = row >> 13;             // N1_DIM == 8192 == 2^13

    const float a = x1[row];
    const float s = scale[0];
    const float Kl = 1.44269504088896340736f / (2.0f * s * s);
    const float C  = -Kl;
    const float Bc = 2.0f * a * Kl;
    const float A  = -a * a * Kl;

    const float4* __restrict__ x2v  = reinterpret_cast<const float4*>(x2) + (size_t)b * (N2_DIM / 4);
    float4* __restrict__       outv = reinterpret_cast<float4*>(out) + (size_t)row * (N2_DIM / 4);

    const int t = threadIdx.x;

    // Front-batched loads for MLP, then compute+streaming stores.
    float4 v[8];
#pragma unroll
    for (int j = 0; j < 8; j++) {
        v[j] = x2v[t + j * 256];           // L1-resident after first row per SM
    }

#pragma unroll
    for (int j = 0; j < 8; j++) {
        float4 r;
        r.x = exp2f(fmaf(fmaf(C, v[j].x, Bc), v[j].x, A));
        r.y = exp2f(fmaf(fmaf(C, v[j].y, Bc), v[j].y, A));
        r.z = exp2f(fmaf(fmaf(C, v[j].z, Bc), v[j].z, A));
        r.w = exp2f(fmaf(fmaf(C, v[j].w, Bc), v[j].w, A));
        // Streaming store: output is written once and never re-read;
        // evict-first keeps x2 hot in L2.
        __stcs(&outv[t + j * 256], r);
    }
}

extern "C" void kernel_launch(void* const* d_in, const int* in_sizes, int n_in,
                              void* d_out, int out_size)
{
    const float* x1    = (const float*)d_in[0];
    const float* x2    = (const float*)d_in[1];
    const float* scale = (const float*)d_in[2];
    float*       out   = (float*)d_out;

    (void)in_sizes; (void)n_in; (void)out_size;

    rbf_row_kernel<<<B_DIM * N1_DIM, 256>>>(x1, x2, scale, out);
}